// round 1
// baseline (speedup 1.0000x reference)
#include <cuda_runtime.h>
#include <cstdint>

// Problem constants
#define B_TOT   256
#define IN_CAPS 3200
#define NJ      8
#define NM      16
#define NN      8
#define JM      (NJ * NM)          // 128

// Tiling
#define IC      32                 // input caps per chunk
#define NCHUNK  (IN_CAPS / IC)     // 100
#define BPC     64                 // batch elems per CTA (16 warps x 4)
#define NBB     (B_TOT / BPC)      // 4
#define WSTRIDE 132                // padded floats per (i,j) row in SMEM
#define SMEM_BYTES (IC * NJ * WSTRIDE * 4)   // 135168 B

// Scratch (static device arrays; no runtime allocation)
__device__ float g_logits[(size_t)B_TOT * IN_CAPS * NJ];   // 26.2 MB
__device__ float g_part[(size_t)NCHUNK * B_TOT * JM];      // 13.1 MB
__device__ float g_v[B_TOT * JM];                          // v between passes

typedef unsigned long long ull;

__device__ __forceinline__ ull pk2(float a, float b) {
    ull r; asm("mov.b64 %0, {%1, %2};" : "=l"(r) : "f"(a), "f"(b)); return r;
}
__device__ __forceinline__ void upk2(float& a, float& b, ull x) {
    asm("mov.b64 {%0, %1}, %2;" : "=f"(a), "=f"(b) : "l"(x));
}
// packed f32x2 fma: d = a*b + d  (2 fp32 FMAs per instruction)
__device__ __forceinline__ void fma2(ull& d, ull a, ull b) {
    asm("fma.rn.f32x2 %0, %1, %2, %0;" : "+l"(d) : "l"(a), "l"(b));
}

// MODE 0: uniform c = 1/8 (iteration 0).
// MODE 1: a = u.v0; logits = a (stored); c = softmax_j(a).
// MODE 2: a = u.v1; logits = stored + a; c = softmax_j(logits).
// Each accumulates s-partials per (chunk, b, j, m) into g_part.
template <int MODE>
__global__ void __launch_bounds__(512, 1) routing_pass(
    const float* __restrict__ x, const float* __restrict__ W)
{
    extern __shared__ float Ws[];   // [IC][NJ][WSTRIDE]
    const int chunk = blockIdx.x;
    const int bblk  = blockIdx.y;
    const int tid   = threadIdx.x;
    const int i0    = chunk * IC;

    // Stage W[i0:i0+IC] into SMEM. Source is contiguous 128-float rows per (i,j);
    // dest rows are padded to 132 floats (bank-conflict-free j access later).
    {
        const float4* Wg = (const float4*)(W + (size_t)i0 * NJ * NN * NM);
        #pragma unroll 4
        for (int q = tid; q < IC * NJ * 32; q += 512) {
            float4 w = Wg[q];
            int ij = q >> 5, r = q & 31;
            *(float4*)&Ws[ij * WSTRIDE + r * 4] = w;
        }
    }
    __syncthreads();

    const int wrp  = tid >> 5;
    const int lane = tid & 31;
    const int j    = lane >> 2;           // lanes {j*4 .. j*4+3} share j
    const int b    = bblk * BPC + wrp * 4 + (lane & 3);

    // v_prev for this (b, j), packed as 8 f32x2 pairs — lives in regs whole kernel
    ull v2[8];
    if (MODE) {
        const float* vp = g_v + b * JM + j * NM;
        #pragma unroll
        for (int k = 0; k < 8; k++) v2[k] = pk2(vp[2 * k], vp[2 * k + 1]);
    }

    ull s2[8];
    #pragma unroll
    for (int k = 0; k < 8; k++) s2[k] = 0ull;

    const float* xbase = x + ((size_t)b * IN_CAPS + i0) * NN;
    float4 xa = *(const float4*)(xbase);
    float4 xb = *(const float4*)(xbase + 4);

    #pragma unroll 1
    for (int il = 0; il < IC; il++) {
        // prefetch prev logit early (MODE 2) — hidden under the u_hat FMAs
        float prevl = 0.f;
        if (MODE == 2)
            prevl = g_logits[((size_t)b * IN_CAPS + i0 + il) * NJ + j];

        float4 cxa = xa, cxb = xb;
        if (il + 1 < IC) {                 // prefetch next x[b, i+1, :]
            xa = *(const float4*)(xbase + (size_t)(il + 1) * NN);
            xb = *(const float4*)(xbase + (size_t)(il + 1) * NN + 4);
        }
        // broadcast each x_n into both halves of an f32x2
        ull x2[8];
        x2[0] = pk2(cxa.x, cxa.x); x2[1] = pk2(cxa.y, cxa.y);
        x2[2] = pk2(cxa.z, cxa.z); x2[3] = pk2(cxa.w, cxa.w);
        x2[4] = pk2(cxb.x, cxb.x); x2[5] = pk2(cxb.y, cxb.y);
        x2[6] = pk2(cxb.z, cxb.z); x2[7] = pk2(cxb.w, cxb.w);

        // u_hat[m0:16] for this (b, i, j): 64 packed FMAs + 32 LDS128
        ull u2[8];
        #pragma unroll
        for (int k = 0; k < 8; k++) u2[k] = 0ull;
        const float* wp = &Ws[(il * NJ + j) * WSTRIDE];
        #pragma unroll
        for (int n = 0; n < 8; n++) {
            const ulonglong2* wv = (const ulonglong2*)(wp + n * 16);
            ulonglong2 w0 = wv[0], w1 = wv[1], w2_ = wv[2], w3 = wv[3];
            fma2(u2[0], w0.x,  x2[n]); fma2(u2[1], w0.y,  x2[n]);
            fma2(u2[2], w1.x,  x2[n]); fma2(u2[3], w1.y,  x2[n]);
            fma2(u2[4], w2_.x, x2[n]); fma2(u2[5], w2_.y, x2[n]);
            fma2(u2[6], w3.x,  x2[n]); fma2(u2[7], w3.y,  x2[n]);
        }

        float c;
        if (MODE == 0) {
            c = 0.125f;
        } else {
            // a = sum_m v[m] * u[m]
            ull acc = 0ull;
            #pragma unroll
            for (int k = 0; k < 8; k++) fma2(acc, u2[k], v2[k]);
            float al, ah; upk2(al, ah, acc);
            float a = al + ah;
            float logit;
            if (MODE == 1) {
                g_logits[((size_t)b * IN_CAPS + i0 + il) * NJ + j] = a;
                logit = a;
            } else {
                logit = prevl + a;
            }
            // softmax over the 8 j-lanes of the same b (lane bits 2..4)
            float mx = logit;
            mx = fmaxf(mx, __shfl_xor_sync(0xffffffffu, mx, 4));
            mx = fmaxf(mx, __shfl_xor_sync(0xffffffffu, mx, 8));
            mx = fmaxf(mx, __shfl_xor_sync(0xffffffffu, mx, 16));
            float e = __expf(logit - mx);
            float sm = e;
            sm += __shfl_xor_sync(0xffffffffu, sm, 4);
            sm += __shfl_xor_sync(0xffffffffu, sm, 8);
            sm += __shfl_xor_sync(0xffffffffu, sm, 16);
            c = __fdividef(e, sm);
        }
        ull c2 = pk2(c, c);
        #pragma unroll
        for (int k = 0; k < 8; k++) fma2(s2[k], u2[k], c2);
    }

    // write s-partials for this chunk
    float* pp = g_part + ((size_t)chunk * B_TOT + b) * JM + j * NM;
    #pragma unroll
    for (int k = 0; k < 8; k++) {
        float lo, hi; upk2(lo, hi, s2[k]);
        *(float2*)&pp[2 * k] = make_float2(lo, hi);
    }
}

// Sum partials over chunks (deterministic order), apply squash, write v.
__global__ void __launch_bounds__(128) reduce_squash(float* __restrict__ vout)
{
    const int b = blockIdx.x, t = threadIdx.x;  // t = j*16 + m
    const float* p = g_part + (size_t)b * JM + t;
    float s = 0.f;
    #pragma unroll 4
    for (int k = 0; k < NCHUNK; k++) s += p[(size_t)k * B_TOT * JM];
    __shared__ float sh[JM];
    sh[t] = s;
    __syncthreads();
    const int j = t >> 4;
    float sq = 0.f;
    #pragma unroll
    for (int m = 0; m < NM; m++) { float z = sh[j * NM + m]; sq += z * z; }
    float f = sq / ((1.0f + sq) * sqrtf(sq));
    vout[b * JM + t] = s * f;
}

extern "C" void kernel_launch(void* const* d_in, const int* in_sizes, int n_in,
                              void* d_out, int out_size)
{
    const float* x = (const float*)d_in[0];
    const float* W = (const float*)d_in[1];
    // defensive: identify by element count (x: 6,553,600; W: 3,276,800)
    if (n_in >= 2 && in_sizes[0] == IN_CAPS * NJ * NN * NM) {
        W = (const float*)d_in[0];
        x = (const float*)d_in[1];
    }

    cudaFuncSetAttribute(routing_pass<0>, cudaFuncAttributeMaxDynamicSharedMemorySize, SMEM_BYTES);
    cudaFuncSetAttribute(routing_pass<1>, cudaFuncAttributeMaxDynamicSharedMemorySize, SMEM_BYTES);
    cudaFuncSetAttribute(routing_pass<2>, cudaFuncAttributeMaxDynamicSharedMemorySize, SMEM_BYTES);

    float* vbuf = nullptr;
    cudaGetSymbolAddress((void**)&vbuf, g_v);

    dim3 grid(NCHUNK, NBB);

    // iteration 0: c uniform -> s0 -> v0
    routing_pass<0><<<grid, 512, SMEM_BYTES>>>(x, W);
    reduce_squash<<<B_TOT, 128>>>(vbuf);
    // iteration 1: logits = a(v0); c = softmax -> s1 -> v1
    routing_pass<1><<<grid, 512, SMEM_BYTES>>>(x, W);
    reduce_squash<<<B_TOT, 128>>>(vbuf);
    // final: logits += a(v1); c = softmax -> s2 -> v2 = output
    routing_pass<2><<<grid, 512, SMEM_BYTES>>>(x, W);
    reduce_squash<<<B_TOT, 128>>>((float*)d_out);
}

// round 3
// speedup vs baseline: 1.0860x; 1.0860x over previous
#include <cuda_runtime.h>
#include <cstdint>

// Problem constants
#define B_TOT   256
#define IN_CAPS 3200
#define NJ      8
#define NM      16
#define NN      8
#define JM      (NJ * NM)          // 128

// Tiling
#define IC      32                 // input caps per chunk
#define NCHUNK  (IN_CAPS / IC)     // 100
#define BPC     64                 // batch elems per CTA (16 warps x 4)
#define NBB     (B_TOT / BPC)      // 4
#define WSTRIDE 132                // padded floats per (i,j) row in SMEM
#define SMEM_BYTES (IC * NJ * WSTRIDE * 4)   // 135168 B

// Scratch (static device arrays; no runtime allocation)
__device__ float g_logits[(size_t)B_TOT * IN_CAPS * NJ];   // 26.2 MB
__device__ float g_part[(size_t)NCHUNK * B_TOT * JM];      // 13.1 MB
__device__ float g_v[B_TOT * JM];                          // v between passes

typedef unsigned long long ull;

__device__ __forceinline__ ull pk2(float a, float b) {
    ull r; asm("mov.b64 %0, {%1, %2};" : "=l"(r) : "f"(a), "f"(b)); return r;
}
__device__ __forceinline__ void upk2(float& a, float& b, ull x) {
    asm("mov.b64 {%0, %1}, %2;" : "=f"(a), "=f"(b) : "l"(x));
}
// packed f32x2 fma: d = a*b + d  (2 fp32 FMAs per instruction)
__device__ __forceinline__ void fma2(ull& d, ull a, ull b) {
    asm("fma.rn.f32x2 %0, %1, %2, %0;" : "+l"(d) : "l"(a), "l"(b));
}

// u2[0:8] (16 floats packed) = W_row . x  for one (i,j)
__device__ __forceinline__ void compute_u(ull* u2, const float* wp, const ull* x2) {
    #pragma unroll
    for (int k = 0; k < 8; k++) u2[k] = 0ull;
    #pragma unroll
    for (int n = 0; n < 8; n++) {
        const ulonglong2* wv = (const ulonglong2*)(wp + n * 16);
        ulonglong2 w0 = wv[0], w1 = wv[1], w2_ = wv[2], w3 = wv[3];
        fma2(u2[0], w0.x,  x2[n]); fma2(u2[1], w0.y,  x2[n]);
        fma2(u2[2], w1.x,  x2[n]); fma2(u2[3], w1.y,  x2[n]);
        fma2(u2[4], w2_.x, x2[n]); fma2(u2[5], w2_.y, x2[n]);
        fma2(u2[6], w3.x,  x2[n]); fma2(u2[7], w3.y,  x2[n]);
    }
}

// softmax over the 8 j-lanes (lane bits 2..4); logits are O(0.1) so no max-sub
__device__ __forceinline__ float softmax8(float logit) {
    float e = __expf(logit);
    float sm = e;
    sm += __shfl_xor_sync(0xffffffffu, sm, 4);
    sm += __shfl_xor_sync(0xffffffffu, sm, 8);
    sm += __shfl_xor_sync(0xffffffffu, sm, 16);
    return __fdividef(e, sm);
}

__device__ __forceinline__ float dot16(const ull* u2, const ull* v2) {
    ull acc = 0ull;
    #pragma unroll
    for (int k = 0; k < 8; k++) fma2(acc, u2[k], v2[k]);
    float al, ah; upk2(al, ah, acc);
    return al + ah;
}

// MODE 0: uniform c = 1/8 (iteration 0) — direct accumulation, scale at end.
// MODE 1: a = u.v0; logits = a (stored); c = softmax_j(a).
// MODE 2: a = u.v1; logits = stored + a; c = softmax_j(logits).
// MODE 1/2 are software-pipelined: s += c_prev*u_prev happens one iter late so
// the softmax dependent chain is hidden under the next iteration's FMA block.
template <int MODE>
__global__ void __launch_bounds__(512, 1) routing_pass(
    const float* __restrict__ x, const float* __restrict__ W)
{
    extern __shared__ float Ws[];   // [IC][NJ][WSTRIDE]
    const int chunk = blockIdx.x;
    const int bblk  = blockIdx.y;
    const int tid   = threadIdx.x;
    const int i0    = chunk * IC;

    // Stage W[i0:i0+IC] into SMEM (padded rows -> conflict-free j access).
    {
        const float4* Wg = (const float4*)(W + (size_t)i0 * NJ * NN * NM);
        #pragma unroll 4
        for (int q = tid; q < IC * NJ * 32; q += 512) {
            float4 w = Wg[q];
            int ij = q >> 5, r = q & 31;
            *(float4*)&Ws[ij * WSTRIDE + r * 4] = w;
        }
    }
    __syncthreads();

    const int wrp  = tid >> 5;
    const int lane = tid & 31;
    const int j    = lane >> 2;           // lanes {j*4 .. j*4+3} share j
    const int b    = bblk * BPC + wrp * 4 + (lane & 3);

    // v_prev for this (b, j), packed — lives in regs the whole kernel
    ull v2[8];
    if (MODE) {
        const float* vp = g_v + b * JM + j * NM;
        #pragma unroll
        for (int k = 0; k < 8; k++) v2[k] = pk2(vp[2 * k], vp[2 * k + 1]);
    }

    ull s2[8];
    #pragma unroll
    for (int k = 0; k < 8; k++) s2[k] = 0ull;

    const float* xbase = x + ((size_t)b * IN_CAPS + i0) * NN;
    float* lbase = g_logits + ((size_t)b * IN_CAPS + i0) * NJ + j;
    float4 xa = *(const float4*)(xbase);
    float4 xb = *(const float4*)(xbase + 4);

    ull xcur[8];
    #define PREP_X(il)                                                        \
        {   float4 cxa = xa, cxb = xb;                                        \
            if ((il) + 1 < IC) {                                              \
                xa = *(const float4*)(xbase + (size_t)((il) + 1) * NN);       \
                xb = *(const float4*)(xbase + (size_t)((il) + 1) * NN + 4);   \
            }                                                                 \
            xcur[0] = pk2(cxa.x, cxa.x); xcur[1] = pk2(cxa.y, cxa.y);         \
            xcur[2] = pk2(cxa.z, cxa.z); xcur[3] = pk2(cxa.w, cxa.w);         \
            xcur[4] = pk2(cxb.x, cxb.x); xcur[5] = pk2(cxb.y, cxb.y);         \
            xcur[6] = pk2(cxb.z, cxb.z); xcur[7] = pk2(cxb.w, cxb.w);         \
        }

    if (MODE == 0) {
        // s += (1/8) * sum_i u  -> accumulate u straight into s2, scale at end
        #pragma unroll 2
        for (int il = 0; il < IC; il++) {
            PREP_X(il);
            const float* wp = &Ws[(il * NJ + j) * WSTRIDE];
            #pragma unroll
            for (int n = 0; n < 8; n++) {
                const ulonglong2* wv = (const ulonglong2*)(wp + n * 16);
                ulonglong2 w0 = wv[0], w1 = wv[1], w2_ = wv[2], w3 = wv[3];
                fma2(s2[0], w0.x,  xcur[n]); fma2(s2[1], w0.y,  xcur[n]);
                fma2(s2[2], w1.x,  xcur[n]); fma2(s2[3], w1.y,  xcur[n]);
                fma2(s2[4], w2_.x, xcur[n]); fma2(s2[5], w2_.y, xcur[n]);
                fma2(s2[6], w3.x,  xcur[n]); fma2(s2[7], w3.y,  xcur[n]);
            }
        }
        #pragma unroll
        for (int k = 0; k < 8; k++) {
            float lo, hi; upk2(lo, hi, s2[k]);
            s2[k] = pk2(lo * 0.125f, hi * 0.125f);
        }
    } else {
        ull up[8];
        float c_prev;
        // prologue: il = 0
        {
            float prevl = (MODE == 2) ? lbase[0] : 0.f;
            PREP_X(0);
            compute_u(up, &Ws[(0 * NJ + j) * WSTRIDE], xcur);
            float a = dot16(up, v2);
            float logit = (MODE == 1) ? a : (prevl + a);
            if (MODE == 1) lbase[0] = a;
            c_prev = softmax8(logit);
        }
        #pragma unroll 2
        for (int il = 1; il < IC; il++) {
            float prevl = (MODE == 2) ? lbase[(size_t)il * NJ] : 0.f;
            PREP_X(il);
            ull uc[8];
            compute_u(uc, &Ws[(il * NJ + j) * WSTRIDE], xcur);
            // apply previous iteration's routing weight (softmax long done)
            ull c2 = pk2(c_prev, c_prev);
            #pragma unroll
            for (int k = 0; k < 8; k++) fma2(s2[k], up[k], c2);
            float a = dot16(uc, v2);
            float logit = (MODE == 1) ? a : (prevl + a);
            if (MODE == 1) lbase[(size_t)il * NJ] = a;
            c_prev = softmax8(logit);
            #pragma unroll
            for (int k = 0; k < 8; k++) up[k] = uc[k];
        }
        // tail
        ull c2 = pk2(c_prev, c_prev);
        #pragma unroll
        for (int k = 0; k < 8; k++) fma2(s2[k], up[k], c2);
    }

    // write s-partials for this chunk
    float* pp = g_part + ((size_t)chunk * B_TOT + b) * JM + j * NM;
    #pragma unroll
    for (int k = 0; k < 8; k++) {
        float lo, hi; upk2(lo, hi, s2[k]);
        *(float2*)&pp[2 * k] = make_float2(lo, hi);
    }
    #undef PREP_X
}

// Sum partials over chunks (4 parallel groups of 25, deterministic), squash, write v.
__global__ void __launch_bounds__(512) reduce_squash(float* __restrict__ vout)
{
    const int b = blockIdx.x, t = threadIdx.x;
    const int g = t >> 7, w = t & 127;        // group 0..3, element 0..127
    __shared__ float sh[4][JM];

    const float* p = g_part + ((size_t)(g * 25) * B_TOT + b) * JM + w;
    float a0 = 0.f, a1 = 0.f, a2 = 0.f, a3 = 0.f;
    #pragma unroll
    for (int k = 0; k < 24; k += 4) {
        a0 += p[(size_t)(k + 0) * B_TOT * JM];
        a1 += p[(size_t)(k + 1) * B_TOT * JM];
        a2 += p[(size_t)(k + 2) * B_TOT * JM];
        a3 += p[(size_t)(k + 3) * B_TOT * JM];
    }
    a0 += p[(size_t)24 * B_TOT * JM];
    sh[g][w] = (a0 + a1) + (a2 + a3);
    __syncthreads();

    if (t < JM) {
        float tot = ((sh[0][t] + sh[1][t]) + (sh[2][t] + sh[3][t]));
        const int j = t >> 4;
        float sq = 0.f;
        #pragma unroll
        for (int m = 0; m < NM; m++) {
            int e = j * NM + m;
            float z = ((sh[0][e] + sh[1][e]) + (sh[2][e] + sh[3][e]));
            sq += z * z;
        }
        float f = sq / ((1.0f + sq) * sqrtf(sq));
        vout[b * JM + t] = tot * f;
    }
}

extern "C" void kernel_launch(void* const* d_in, const int* in_sizes, int n_in,
                              void* d_out, int out_size)
{
    const float* x = (const float*)d_in[0];
    const float* W = (const float*)d_in[1];
    // defensive: identify by element count (x: 6,553,600; W: 3,276,800)
    if (n_in >= 2 && in_sizes[0] == IN_CAPS * NJ * NN * NM) {
        W = (const float*)d_in[0];
        x = (const float*)d_in[1];
    }

    cudaFuncSetAttribute(routing_pass<0>, cudaFuncAttributeMaxDynamicSharedMemorySize, SMEM_BYTES);
    cudaFuncSetAttribute(routing_pass<1>, cudaFuncAttributeMaxDynamicSharedMemorySize, SMEM_BYTES);
    cudaFuncSetAttribute(routing_pass<2>, cudaFuncAttributeMaxDynamicSharedMemorySize, SMEM_BYTES);

    float* vbuf = nullptr;
    cudaGetSymbolAddress((void**)&vbuf, g_v);

    dim3 grid(NCHUNK, NBB);

    // iteration 0: c uniform -> s0 -> v0
    routing_pass<0><<<grid, 512, SMEM_BYTES>>>(x, W);
    reduce_squash<<<B_TOT, 512>>>(vbuf);
    // iteration 1: logits = a(v0); c = softmax -> s1 -> v1
    routing_pass<1><<<grid, 512, SMEM_BYTES>>>(x, W);
    reduce_squash<<<B_TOT, 512>>>(vbuf);
    // final: logits += a(v1); c = softmax -> s2 -> v2 = output
    routing_pass<2><<<grid, 512, SMEM_BYTES>>>(x, W);
    reduce_squash<<<B_TOT, 512>>>((float*)d_out);
}